// round 14
// baseline (speedup 1.0000x reference)
#include <cuda_runtime.h>
#include <cuda_bf16.h>
#include <cstdint>

#define N_NODES 10000
#define N_EDGES 160000
#define C_IN    1024
#define C_OUT   512
#define KP      3072                       // 3-way split K'
#define NOUT    ((size_t)N_NODES * C_OUT)

// ---------------- scratch (static device globals; no allocations) ----------
// NOTE 1: module-static budget is load-bearing (~170 MB works, 230 MB breaks
// module load). Statics ~137 MB.
// NOTE 2: never pass g_* globals as kernel args from host code (host-side
// shadow address + ATS = silent garbage). Reference them in device code only.
__device__ float g_sx   [(size_t)N_NODES * C_IN];   // bf16 [hi|lo] A for GEMM0 (written by spmm)
__device__ float g_h    [(size_t)N_NODES * 1024];   // fp32 hidden
__device__ float g_sh   [(size_t)N_NODES * 1024];   // bf16 [hi|lo] A for GEMM1 (written by spmm)
__device__ float g_colsum [C_IN];
__device__ float g_colsum2[C_IN];
__device__ float g_A[C_IN];
__device__ float g_B[C_IN];
__device__ float g_dis[N_NODES];
__device__ int   g_deg[N_NODES];
__device__ int   g_ei32[2 * N_EDGES];
__device__ int   g_flag32;
// CSR by destination
__device__ int   g_rowptr[N_NODES + 1];
__device__ int   g_cursor[N_NODES];
__device__ int   g_esrc[N_EDGES];
__device__ float g_ew  [N_EDGES];
// bf16 B operands [n][k'], K-segments [hi, hi, lo]; two buffers so both
// convB's can run concurrently on a side stream (6.3 MB each)
__device__ __nv_bfloat16 g_bh0[(size_t)1024 * KP];
__device__ __nv_bfloat16 g_bh1[(size_t)1024 * KP];

// ---------------- asm helpers ------------------------------------------------
__device__ __forceinline__ uint32_t s2u(const void* p) {
    uint32_t a;
    asm("{ .reg .u64 t; cvta.to.shared.u64 t, %1; cvt.u32.u64 %0, t; }"
        : "=r"(a) : "l"(p));
    return a;
}
__device__ __forceinline__ void ldsm4(uint32_t* r, uint32_t addr) {
    asm volatile("ldmatrix.sync.aligned.m8n8.x4.shared.b16 {%0,%1,%2,%3}, [%4];"
                 : "=r"(r[0]), "=r"(r[1]), "=r"(r[2]), "=r"(r[3]) : "r"(addr));
}
__device__ __forceinline__ void mma16816(float* d, const uint32_t* a, const uint32_t* b) {
    asm volatile(
        "mma.sync.aligned.m16n8k16.row.col.f32.bf16.bf16.f32 "
        "{%0,%1,%2,%3}, {%4,%5,%6,%7}, {%8,%9}, {%0,%1,%2,%3};"
        : "+f"(d[0]), "+f"(d[1]), "+f"(d[2]), "+f"(d[3])
        : "r"(a[0]), "r"(a[1]), "r"(a[2]), "r"(a[3]), "r"(b[0]), "r"(b[1]));
}
#define CPA16(dst, src) \
    asm volatile("cp.async.cg.shared.global [%0], [%1], 16;" \
                 :: "r"(dst), "l"(src))

// ---------------- setup kernels --------------------------------------------
__global__ void zero_k() {
    int i = blockIdx.x * blockDim.x + threadIdx.x;
    if (i < C_IN)    { g_colsum[i] = 0.f; g_colsum2[i] = 0.f; }
    if (i < N_NODES) { g_deg[i] = 0; }
    if (i == 0)      { g_flag32 = 0; }
}

__global__ void detect_k(const long long* __restrict__ ei) {
    int i = blockIdx.x * blockDim.x + threadIdx.x;
    if (i < N_EDGES) {
        long long v = ei[i];
        if (v < 0 || v >= N_NODES) atomicOr(&g_flag32, 1);
    }
}

// convert + fused degree histogram (dst half)
__global__ void convert_k(const void* __restrict__ ei) {
    int i = blockIdx.x * blockDim.x + threadIdx.x;
    if (i >= 2 * N_EDGES) return;
    int v = g_flag32 ? ((const int*)ei)[i]
                     : (int)((const long long*)ei)[i];
    g_ei32[i] = v;
    if (i >= N_EDGES) atomicAdd(&g_deg[v], 1);
}

__global__ void colstats_k(const float* __restrict__ x) {
    int col = blockIdx.x * 256 + threadIdx.x;
    int r0  = blockIdx.y * 25;
    float s = 0.f, s2 = 0.f;
    for (int r = r0; r < r0 + 25; r++) {
        float v = x[(size_t)r * C_IN + col];
        s += v; s2 += v * v;
    }
    atomicAdd(&g_colsum[col], s);
    atomicAdd(&g_colsum2[col], s2);
}

__global__ void stats_k(const float* __restrict__ w, const float* __restrict__ b,
                        const float* __restrict__ ms) {
    int j = blockIdx.x * blockDim.x + threadIdx.x;
    if (j >= C_IN) return;
    float m   = g_colsum[j]  * (1.f / N_NODES);
    float ex2 = g_colsum2[j] * (1.f / N_NODES);
    float s   = ms[j];
    float var = ex2 - 2.f * s * m * m + s * s * m * m;
    float Aj  = rsqrtf(var + 1e-5f) * w[j];
    g_A[j] = Aj;
    g_B[j] = b[j] - s * m * Aj;
}

// Single-block exclusive scan of g_deg -> rowptr/cursor; fused g_dis compute.
__global__ void scan_k() {
    __shared__ int ps[1024];
    int t = threadIdx.x;
    int base = t * 10;
    int loc[10];
    int sum = 0;
    #pragma unroll
    for (int i = 0; i < 10; i++) {
        int idx = base + i;
        int v = (idx < N_NODES) ? g_deg[idx] : 0;
        if (idx < N_NODES) g_dis[idx] = rsqrtf((float)v + 1.0f);
        loc[i] = sum;
        sum += v;
    }
    ps[t] = sum;
    __syncthreads();
    for (int off = 1; off < 1024; off <<= 1) {
        int v = (t >= off) ? ps[t - off] : 0;
        __syncthreads();
        ps[t] += v;
        __syncthreads();
    }
    int excl = ps[t] - sum;
    #pragma unroll
    for (int i = 0; i < 10; i++) {
        int idx = base + i;
        if (idx < N_NODES) {
            int p = excl + loc[i];
            g_rowptr[idx] = p;
            g_cursor[idx] = p;
        }
    }
    if (t == 1023) g_rowptr[N_NODES] = ps[1023];
}

__global__ void scatter_k() {
    int e = blockIdx.x * blockDim.x + threadIdx.x;
    if (e >= N_EDGES) return;
    int s = g_ei32[e];
    int d = g_ei32[N_EDGES + e];
    int pos = atomicAdd(&g_cursor[d], 1);
    g_esrc[pos] = s;
    g_ew[pos]   = g_dis[s] * g_dis[d];
}

// CSR pull SpMM fused with bf16 [hi|lo] split.
// PH 0: feat = raw x, GraphNorm fused by linearity:
//       sum w*(A∘x+B) = A∘(sum w*x) + (sum w)*B
// PH 1: feat = g_h (fp32 hidden), no norm.
template<int PH>
__global__ __launch_bounds__(256) void spmm_pull(const float* __restrict__ xin) {
    const float4* __restrict__ feat = (PH == 0) ? (const float4*)xin
                                                : (const float4*)g_h;
    __nv_bfloat16* __restrict__ out = (__nv_bfloat16*)((PH == 0) ? g_sx : g_sh);
    int d = blockIdx.x;
    int t = threadIdx.x;
    int beg = g_rowptr[d], end = g_rowptr[d + 1];
    float dd = g_dis[d]; dd *= dd;
    float4 v0 = feat[(size_t)d * 256 + t];
    float4 acc = make_float4(dd * v0.x, dd * v0.y, dd * v0.z, dd * v0.w);
    float wsum = dd;
    int   sn = (beg < end) ? __ldg(&g_esrc[beg]) : 0;
    float wn = (beg < end) ? __ldg(&g_ew[beg])   : 0.f;
    for (int j = beg; j < end; j++) {
        int s = sn; float w = wn;
        if (j + 1 < end) { sn = __ldg(&g_esrc[j + 1]); wn = __ldg(&g_ew[j + 1]); }
        float4 v = feat[(size_t)s * 256 + t];
        acc.x = fmaf(w, v.x, acc.x);
        acc.y = fmaf(w, v.y, acc.y);
        acc.z = fmaf(w, v.z, acc.z);
        acc.w = fmaf(w, v.w, acc.w);
        wsum += w;
    }
    if (PH == 0) {
        float4 Av = ((const float4*)g_A)[t];
        float4 Bv = ((const float4*)g_B)[t];
        acc.x = fmaf(Av.x, acc.x, wsum * Bv.x);
        acc.y = fmaf(Av.y, acc.y, wsum * Bv.y);
        acc.z = fmaf(Av.z, acc.z, wsum * Bv.z);
        acc.w = fmaf(Av.w, acc.w, wsum * Bv.w);
    }
    __nv_bfloat162 h01 = __floats2bfloat162_rn(acc.x, acc.y);
    __nv_bfloat162 h23 = __floats2bfloat162_rn(acc.z, acc.w);
    __nv_bfloat162 l01 = __floats2bfloat162_rn(acc.x - __low2float(h01),
                                               acc.y - __high2float(h01));
    __nv_bfloat162 l23 = __floats2bfloat162_rn(acc.z - __low2float(h23),
                                               acc.w - __high2float(h23));
    __nv_bfloat16* base = out + (size_t)d * 2048;
    uint2 hv, lv;
    hv.x = *(uint32_t*)&h01; hv.y = *(uint32_t*)&h23;
    lv.x = *(uint32_t*)&l01; lv.y = *(uint32_t*)&l23;
    *(uint2*)(base + t * 4)        = hv;
    *(uint2*)(base + 1024 + t * 4) = lv;
}

// ---------------- B conversion: fp32 W [k][n] -> g_bhX [n][3072] [hi,hi,lo] --
template<int MODE>
__global__ void convB_k(const float* __restrict__ p0, const float* __restrict__ p1) {
    __nv_bfloat16* __restrict__ gbh = (MODE == 0) ? g_bh0 : g_bh1;
    __shared__ float t[32][33];
    int n0 = blockIdx.x * 32, k0 = blockIdx.y * 32;
    int tx = threadIdx.x, ty = threadIdx.y;         // block (32, 8)
    #pragma unroll
    for (int j = 0; j < 32; j += 8) {
        int k = k0 + ty + j, n = n0 + tx;
        float v;
        if (MODE == 0) v = p0[(size_t)k * 1024 + n];
        else           v = (n < 512) ? p0[(size_t)k * 512 + n]
                                     : p1[(size_t)k * 512 + (n - 512)];
        t[ty + j][tx] = v;
    }
    __syncthreads();
    #pragma unroll
    for (int j = 0; j < 32; j += 8) {
        int n = n0 + ty + j, k = k0 + tx;
        float v = t[tx][ty + j];
        __nv_bfloat16 h = __float2bfloat16(v);
        __nv_bfloat16 l = __float2bfloat16(v - __bfloat162float(h));
        size_t b = (size_t)n * KP + k;
        gbh[b]        = h;
        gbh[b + 1024] = h;
        gbh[b + 2048] = l;
    }
}

// ---------------- mma.sync bf16 GEMM -----------------------------------------
// CTA 256x128, 512 threads, 16 warps (8M x 2N), warp tile 32x64 (unchanged
// per-warp fragment math), BK=32, 4-stage cp.async, lookahead-2.
// TM=256 halves B L2 traffic (B re-read 40x instead of 79x).
// 16 warps/SM (1 CTA) == R12's 2x256 occupancy; smem 120KB/CTA.
#define ROWB 40
#define NCH  (KP / 32)           // 96 chunks
#define STG_A (256 * 80)         // 20480 per stage
#define STG_B (128 * 80)         // 10240 per stage
#define SMEM_DYN (4 * (STG_A + STG_B))   // 122880

__device__ __forceinline__ int a_koff(int cn) {
    return (((cn >> 5) == 1) ? 2048 : 0) + (cn & 31) * 64;
}

template<int MODE>
__global__ void __launch_bounds__(512, 1) gemm_mma(const float* __restrict__ bias0,
                                                   const float* __restrict__ bias1,
                                                   float* __restrict__ outp) {
    extern __shared__ char dsm[];
    uint32_t smemA = s2u(dsm);                    // 4 stages x 20480
    uint32_t smemB = smemA + 4 * STG_A;           // 4 stages x 10240

    const __nv_bfloat16* __restrict__ Ap =
        (const __nv_bfloat16*)((MODE == 0) ? g_sx : g_sh);
    const __nv_bfloat16* __restrict__ Bp = (MODE == 0) ? g_bh0 : g_bh1;
    int tid  = threadIdx.x;
    int lane = tid & 31, w = tid >> 5;            // 16 warps
    int wm = w >> 1, wn = w & 1;                  // wm 0..7, wn 0..1
    int g = lane >> 2, tig = lane & 3;
    int row0 = blockIdx.y * 256, col0 = blockIdx.x * 128;

    // loader: per chunk, 2 A txns + 1 B txn per thread (16B each)
    int rA0 = tid >> 2;                 // 0..127
    int rA1 = rA0 + 128;                // 128..255
    int u0b = (tid & 3) * 16;
    int ra0 = row0 + rA0; if (ra0 >= N_NODES) ra0 = N_NODES - 1;
    int ra1 = row0 + rA1; if (ra1 >= N_NODES) ra1 = N_NODES - 1;
    const char* srcA0 = (const char*)(Ap + (size_t)ra0 * 2048) + u0b;
    const char* srcA1 = (const char*)(Ap + (size_t)ra1 * 2048) + u0b;
    const char* srcB0 = (const char*)(Bp + (size_t)(col0 + rA0) * KP) + u0b;
    uint32_t dstA0 = (uint32_t)(rA0 * 80 + u0b);
    uint32_t dstA1 = (uint32_t)(rA1 * 80 + u0b);
    uint32_t dstB0 = (uint32_t)(rA0 * 80 + u0b);

    int quad = lane >> 3, rin = lane & 7;
    uint32_t aLane = (uint32_t)((wm * 32 + (quad & 1) * 8 + rin) * 80 + (quad >> 1) * 16);
    uint32_t bLane = (uint32_t)((wn * 64 + (quad >> 1) * 8 + rin) * 80 + (quad & 1) * 16);

    float acc[2][8][4];
    #pragma unroll
    for (int m = 0; m < 2; m++)
        #pragma unroll
        for (int n = 0; n < 8; n++)
            #pragma unroll
            for (int q = 0; q < 4; q++) acc[m][n][q] = 0.f;

#define LOADCHUNK(cn, st) do {                                            \
        uint32_t as_ = smemA + (st) * STG_A;                              \
        uint32_t bs_ = smemB + (st) * STG_B;                              \
        int ka_ = a_koff(cn);                                             \
        CPA16(as_ + dstA0, srcA0 + ka_);                                  \
        CPA16(as_ + dstA1, srcA1 + ka_);                                  \
        CPA16(bs_ + dstB0, srcB0 + (size_t)(cn) * 64);                    \
        asm volatile("cp.async.commit_group;" ::: "memory");              \
    } while (0)

    // prologue: stages 0,1
    LOADCHUNK(0, 0);
    LOADCHUNK(1, 1);

    #pragma unroll 1
    for (int c = 0; c < NCH; c++) {
        int s = c & 3;
        if (c + 2 < NCH) LOADCHUNK(c + 2, (c + 2) & 3);
        if      (c + 2 < NCH) asm volatile("cp.async.wait_group 2;" ::: "memory");
        else if (c + 1 < NCH) asm volatile("cp.async.wait_group 1;" ::: "memory");
        else                  asm volatile("cp.async.wait_group 0;" ::: "memory");
        __syncthreads();

        uint32_t aBase = smemA + s * STG_A + aLane;
        uint32_t bBase = smemB + s * STG_B + bLane;
        #pragma unroll
        for (int kt = 0; kt < 2; kt++) {
            uint32_t af[2][4];
            ldsm4(af[0], aBase + kt * 32);
            ldsm4(af[1], aBase + 16 * 80 + kt * 32);
            #pragma unroll
            for (int np = 0; np < 4; np++) {
                uint32_t bq[4];
                ldsm4(bq, bBase + np * (16 * 80) + kt * 32);
                #pragma unroll
                for (int mt = 0; mt < 2; mt++) {
                    mma16816(acc[mt][np * 2],     af[mt], bq);
                    mma16816(acc[mt][np * 2 + 1], af[mt], bq + 2);
                }
            }
        }
    }
#undef LOADCHUNK

    // ---- epilogue ----
    #pragma unroll
    for (int mt = 0; mt < 2; mt++) {
        int rlo = row0 + wm * 32 + mt * 16 + g;
        #pragma unroll
        for (int half = 0; half < 2; half++) {
            int row = rlo + half * 8;
            if (row >= N_NODES) continue;
            #pragma unroll
            for (int nt = 0; nt < 8; nt++) {
                int cca = col0 + wn * 64 + nt * 8 + tig * 2;
                float b0, b1v;
                if (MODE == 0) { b0 = __ldg(&bias0[cca]); b1v = __ldg(&bias0[cca + 1]); }
                else if (cca < 512) { b0 = __ldg(&bias0[cca]); b1v = __ldg(&bias0[cca + 1]); }
                else { b0 = __ldg(&bias1[cca - 512]); b1v = __ldg(&bias1[cca - 511]); }
                float v0 = acc[mt][nt][half * 2]     + b0;
                float v1 = acc[mt][nt][half * 2 + 1] + b1v;
                if (MODE == 0) {
                    v0 = (v0 > 0.f) ? v0 : 0.1f * v0;
                    v1 = (v1 > 0.f) ? v1 : 0.1f * v1;
                    *(float2*)&g_h[(size_t)row * 1024 + cca] = make_float2(v0, v1);
                } else {
                    if (cca < C_OUT) {
                        *(float2*)&outp[(size_t)row * C_OUT + cca]        = make_float2(v0, v1);
                        *(float2*)&outp[NOUT + (size_t)row * C_OUT + cca] = make_float2(v0, v1);
                    } else {
                        *(float2*)&outp[2 * NOUT + (size_t)row * C_OUT + (cca - C_OUT)]
                            = make_float2(v0, v1);
                    }
                }
            }
        }
    }
}

// ---------------- launcher --------------------------------------------------
// Capture-fork pattern: side streams join via events recorded on the origin
// (capturing) stream. Streams/events are created on the first call — the
// correctness run, which is NOT captured — and reused; the launched work is
// identical on every call.
extern "C" void kernel_launch(void* const* d_in, const int* in_sizes, int n_in,
                              void* d_out, int out_size) {
    const float* x   = (const float*)d_in[0];
    const void*  ei  = d_in[1];
    const float* W1  = (const float*)d_in[2];
    const float* b1  = (const float*)d_in[3];
    const float* Wm  = (const float*)d_in[4];
    const float* bm  = (const float*)d_in[5];
    const float* Ws  = (const float*)d_in[6];
    const float* bs  = (const float*)d_in[7];
    const float* gw  = (const float*)d_in[8];
    const float* gb  = (const float*)d_in[9];
    const float* gms = (const float*)d_in[10];
    float* out = (float*)d_out;

    static cudaStream_t sB = nullptr, sC = nullptr;
    static cudaEvent_t eFork, eStats, eB0, eB1;
    if (sB == nullptr) {
        cudaStreamCreateWithFlags(&sB, cudaStreamNonBlocking);
        cudaStreamCreateWithFlags(&sC, cudaStreamNonBlocking);
        cudaEventCreateWithFlags(&eFork,  cudaEventDisableTiming);
        cudaEventCreateWithFlags(&eStats, cudaEventDisableTiming);
        cudaEventCreateWithFlags(&eB0,    cudaEventDisableTiming);
        cudaEventCreateWithFlags(&eB1,    cudaEventDisableTiming);
        cudaFuncSetAttribute(gemm_mma<0>, cudaFuncAttributeMaxDynamicSharedMemorySize, SMEM_DYN);
        cudaFuncSetAttribute(gemm_mma<1>, cudaFuncAttributeMaxDynamicSharedMemorySize, SMEM_DYN);
    }

    dim3 gg(1024 / 128, (N_NODES + 255) / 256);   // (8, 40)

    // main stream: zeroing (needed by both branches), then fork
    zero_k<<<40, 256>>>();
    cudaEventRecord(eFork, 0);
    cudaStreamWaitEvent(sB, eFork, 0);
    cudaStreamWaitEvent(sC, eFork, 0);

    // branch B: GraphNorm stats (independent of edges)
    colstats_k<<<dim3(4, 400), 256, 0, sB>>>(x);
    stats_k  <<<4, 256, 0, sB>>>(gw, gb, gms);
    cudaEventRecord(eStats, sB);

    // branch C: both weight conversions (independent of everything else)
    convB_k<0><<<dim3(32, 32), dim3(32, 8), 0, sC>>>(W1, nullptr);
    cudaEventRecord(eB0, sC);
    convB_k<1><<<dim3(32, 32), dim3(32, 8), 0, sC>>>(Wm, Ws);
    cudaEventRecord(eB1, sC);

    // main: edge prep chain
    detect_k <<<(N_EDGES + 255) / 256, 256>>>((const long long*)ei);
    convert_k<<<(2 * N_EDGES + 255) / 256, 256>>>(ei);   // + fused deg
    scan_k   <<<1, 1024>>>();                            // + fused dis
    scatter_k<<<(N_EDGES + 255) / 256, 256>>>();

    // join: spmm0 needs stats; gemm0 needs convB0; gemm1 needs convB1
    cudaStreamWaitEvent(0, eStats, 0);
    spmm_pull<0><<<N_NODES, 256>>>(x);                   // + fused GraphNorm -> bf16 A in g_sx
    cudaStreamWaitEvent(0, eB0, 0);
    gemm_mma<0><<<gg, 512, SMEM_DYN>>>(b1, nullptr, nullptr);
    spmm_pull<1><<<N_NODES, 256>>>(nullptr);             // -> bf16 A in g_sh
    cudaStreamWaitEvent(0, eB1, 0);
    gemm_mma<1><<<gg, 512, SMEM_DYN>>>(bm, bs, out);
}

// round 15
// speedup vs baseline: 1.1505x; 1.1505x over previous
#include <cuda_runtime.h>
#include <cuda_bf16.h>
#include <cstdint>

#define N_NODES 10000
#define N_EDGES 160000
#define C_IN    1024
#define C_OUT   512
#define KP      3072                       // 3-way split K'
#define NOUT    ((size_t)N_NODES * C_OUT)

// ---------------- scratch (static device globals; no allocations) ----------
// NOTE 1: module-static budget is load-bearing (~170 MB works, 230 MB breaks
// module load). Statics ~137 MB.
// NOTE 2: never pass g_* globals as kernel args from host code (host-side
// shadow address + ATS = silent garbage). Reference them in device code only.
// NOTE 3: GEMM config is committed: 128x128 CTA, 256 thr, 4-stage/80KB
// (2 CTAs/SM). R11 (100KB->1 CTA/SM) and R14 (512-thr monolithic CTA) both
// regressed; GEMM is mma.sync-pipe-bound, not L2-bound.
__device__ float g_sx   [(size_t)N_NODES * C_IN];   // bf16 [hi|lo] A for GEMM0 (written by spmm)
__device__ float g_h    [(size_t)N_NODES * 1024];   // fp32 hidden
__device__ float g_sh   [(size_t)N_NODES * 1024];   // bf16 [hi|lo] A for GEMM1 (written by spmm)
__device__ float g_colsum [C_IN];
__device__ float g_colsum2[C_IN];
__device__ float g_A[C_IN];
__device__ float g_B[C_IN];
__device__ float g_dis[N_NODES];
__device__ int   g_deg[N_NODES];
__device__ int   g_ei32[2 * N_EDGES];
__device__ int   g_flag32;
// CSR by destination
__device__ int   g_rowptr[N_NODES + 1];
__device__ int   g_cursor[N_NODES];
__device__ int   g_esrc[N_EDGES];
__device__ float g_ew  [N_EDGES];
// bf16 B operands [n][k'], K-segments [hi, hi, lo]; two buffers so both
// convB's can run concurrently on a side stream (6.3 MB each)
__device__ __nv_bfloat16 g_bh0[(size_t)1024 * KP];
__device__ __nv_bfloat16 g_bh1[(size_t)1024 * KP];

// ---------------- asm helpers ------------------------------------------------
__device__ __forceinline__ uint32_t s2u(const void* p) {
    uint32_t a;
    asm("{ .reg .u64 t; cvta.to.shared.u64 t, %1; cvt.u32.u64 %0, t; }"
        : "=r"(a) : "l"(p));
    return a;
}
__device__ __forceinline__ void ldsm4(uint32_t* r, uint32_t addr) {
    asm volatile("ldmatrix.sync.aligned.m8n8.x4.shared.b16 {%0,%1,%2,%3}, [%4];"
                 : "=r"(r[0]), "=r"(r[1]), "=r"(r[2]), "=r"(r[3]) : "r"(addr));
}
__device__ __forceinline__ void mma16816(float* d, const uint32_t* a, const uint32_t* b) {
    asm volatile(
        "mma.sync.aligned.m16n8k16.row.col.f32.bf16.bf16.f32 "
        "{%0,%1,%2,%3}, {%4,%5,%6,%7}, {%8,%9}, {%0,%1,%2,%3};"
        : "+f"(d[0]), "+f"(d[1]), "+f"(d[2]), "+f"(d[3])
        : "r"(a[0]), "r"(a[1]), "r"(a[2]), "r"(a[3]), "r"(b[0]), "r"(b[1]));
}
#define CPA16(dst, src) \
    asm volatile("cp.async.cg.shared.global [%0], [%1], 16;" \
                 :: "r"(dst), "l"(src))

// ---------------- setup kernels --------------------------------------------
__global__ void zero_k() {
    int i = blockIdx.x * blockDim.x + threadIdx.x;
    if (i < C_IN)    { g_colsum[i] = 0.f; g_colsum2[i] = 0.f; }
    if (i < N_NODES) { g_deg[i] = 0; }
    if (i == 0)      { g_flag32 = 0; }
}

__global__ void detect_k(const long long* __restrict__ ei) {
    int i = blockIdx.x * blockDim.x + threadIdx.x;
    if (i < N_EDGES) {
        long long v = ei[i];
        if (v < 0 || v >= N_NODES) atomicOr(&g_flag32, 1);
    }
}

// convert + fused degree histogram (dst half)
__global__ void convert_k(const void* __restrict__ ei) {
    int i = blockIdx.x * blockDim.x + threadIdx.x;
    if (i >= 2 * N_EDGES) return;
    int v = g_flag32 ? ((const int*)ei)[i]
                     : (int)((const long long*)ei)[i];
    g_ei32[i] = v;
    if (i >= N_EDGES) atomicAdd(&g_deg[v], 1);
}

__global__ void colstats_k(const float* __restrict__ x) {
    int col = blockIdx.x * 256 + threadIdx.x;
    int r0  = blockIdx.y * 25;
    float s = 0.f, s2 = 0.f;
    for (int r = r0; r < r0 + 25; r++) {
        float v = x[(size_t)r * C_IN + col];
        s += v; s2 += v * v;
    }
    atomicAdd(&g_colsum[col], s);
    atomicAdd(&g_colsum2[col], s2);
}

__global__ void stats_k(const float* __restrict__ w, const float* __restrict__ b,
                        const float* __restrict__ ms) {
    int j = blockIdx.x * blockDim.x + threadIdx.x;
    if (j >= C_IN) return;
    float m   = g_colsum[j]  * (1.f / N_NODES);
    float ex2 = g_colsum2[j] * (1.f / N_NODES);
    float s   = ms[j];
    float var = ex2 - 2.f * s * m * m + s * s * m * m;
    float Aj  = rsqrtf(var + 1e-5f) * w[j];
    g_A[j] = Aj;
    g_B[j] = b[j] - s * m * Aj;
}

// Single-block exclusive scan of g_deg -> rowptr/cursor; fused g_dis compute.
__global__ void scan_k() {
    __shared__ int ps[1024];
    int t = threadIdx.x;
    int base = t * 10;
    int loc[10];
    int sum = 0;
    #pragma unroll
    for (int i = 0; i < 10; i++) {
        int idx = base + i;
        int v = (idx < N_NODES) ? g_deg[idx] : 0;
        if (idx < N_NODES) g_dis[idx] = rsqrtf((float)v + 1.0f);
        loc[i] = sum;
        sum += v;
    }
    ps[t] = sum;
    __syncthreads();
    for (int off = 1; off < 1024; off <<= 1) {
        int v = (t >= off) ? ps[t - off] : 0;
        __syncthreads();
        ps[t] += v;
        __syncthreads();
    }
    int excl = ps[t] - sum;
    #pragma unroll
    for (int i = 0; i < 10; i++) {
        int idx = base + i;
        if (idx < N_NODES) {
            int p = excl + loc[i];
            g_rowptr[idx] = p;
            g_cursor[idx] = p;
        }
    }
    if (t == 1023) g_rowptr[N_NODES] = ps[1023];
}

__global__ void scatter_k() {
    int e = blockIdx.x * blockDim.x + threadIdx.x;
    if (e >= N_EDGES) return;
    int s = g_ei32[e];
    int d = g_ei32[N_EDGES + e];
    int pos = atomicAdd(&g_cursor[d], 1);
    g_esrc[pos] = s;
    g_ew[pos]   = g_dis[s] * g_dis[d];
}

// CSR pull SpMM fused with bf16 [hi|lo] split.
// PH 0: feat = raw x, GraphNorm fused by linearity:
//       sum w*(A∘x+B) = A∘(sum w*x) + (sum w)*B
// PH 1: feat = g_h (fp32 hidden), no norm.
// One-deep DATA prefetch: feat[src_{j+1}] loads while edge j accumulates
// (accumulation order unchanged -> bit-identical result).
template<int PH>
__global__ __launch_bounds__(256) void spmm_pull(const float* __restrict__ xin) {
    const float4* __restrict__ feat = (PH == 0) ? (const float4*)xin
                                                : (const float4*)g_h;
    __nv_bfloat16* __restrict__ out = (__nv_bfloat16*)((PH == 0) ? g_sx : g_sh);
    int d = blockIdx.x;
    int t = threadIdx.x;
    int beg = g_rowptr[d], end = g_rowptr[d + 1];
    float dd = g_dis[d]; dd *= dd;
    float4 v0 = feat[(size_t)d * 256 + t];
    float4 acc = make_float4(dd * v0.x, dd * v0.y, dd * v0.z, dd * v0.w);
    float wsum = dd;

    float4 vc = make_float4(0.f, 0.f, 0.f, 0.f);
    float  wc = 0.f;
    int    sn = 0;
    if (beg < end) {
        sn = __ldg(&g_esrc[beg]);
        wc = __ldg(&g_ew[beg]);
        vc = feat[(size_t)sn * 256 + t];
    }
    for (int j = beg; j < end; j++) {
        float4 vn; float wn2 = 0.f;
        if (j + 1 < end) {
            int s2 = __ldg(&g_esrc[j + 1]);
            wn2 = __ldg(&g_ew[j + 1]);
            vn = feat[(size_t)s2 * 256 + t];     // in flight during the FMAs below
        }
        acc.x = fmaf(wc, vc.x, acc.x);
        acc.y = fmaf(wc, vc.y, acc.y);
        acc.z = fmaf(wc, vc.z, acc.z);
        acc.w = fmaf(wc, vc.w, acc.w);
        wsum += wc;
        if (j + 1 < end) { vc = vn; wc = wn2; }
    }

    if (PH == 0) {
        float4 Av = ((const float4*)g_A)[t];
        float4 Bv = ((const float4*)g_B)[t];
        acc.x = fmaf(Av.x, acc.x, wsum * Bv.x);
        acc.y = fmaf(Av.y, acc.y, wsum * Bv.y);
        acc.z = fmaf(Av.z, acc.z, wsum * Bv.z);
        acc.w = fmaf(Av.w, acc.w, wsum * Bv.w);
    }
    __nv_bfloat162 h01 = __floats2bfloat162_rn(acc.x, acc.y);
    __nv_bfloat162 h23 = __floats2bfloat162_rn(acc.z, acc.w);
    __nv_bfloat162 l01 = __floats2bfloat162_rn(acc.x - __low2float(h01),
                                               acc.y - __high2float(h01));
    __nv_bfloat162 l23 = __floats2bfloat162_rn(acc.z - __low2float(h23),
                                               acc.w - __high2float(h23));
    __nv_bfloat16* base = out + (size_t)d * 2048;
    uint2 hv, lv;
    hv.x = *(uint32_t*)&h01; hv.y = *(uint32_t*)&h23;
    lv.x = *(uint32_t*)&l01; lv.y = *(uint32_t*)&l23;
    *(uint2*)(base + t * 4)        = hv;
    *(uint2*)(base + 1024 + t * 4) = lv;
}

// ---------------- B conversion: fp32 W [k][n] -> g_bhX [n][3072] [hi,hi,lo] --
template<int MODE>
__global__ void convB_k(const float* __restrict__ p0, const float* __restrict__ p1) {
    __nv_bfloat16* __restrict__ gbh = (MODE == 0) ? g_bh0 : g_bh1;
    __shared__ float t[32][33];
    int n0 = blockIdx.x * 32, k0 = blockIdx.y * 32;
    int tx = threadIdx.x, ty = threadIdx.y;         // block (32, 8)
    #pragma unroll
    for (int j = 0; j < 32; j += 8) {
        int k = k0 + ty + j, n = n0 + tx;
        float v;
        if (MODE == 0) v = p0[(size_t)k * 1024 + n];
        else           v = (n < 512) ? p0[(size_t)k * 512 + n]
                                     : p1[(size_t)k * 512 + (n - 512)];
        t[ty + j][tx] = v;
    }
    __syncthreads();
    #pragma unroll
    for (int j = 0; j < 32; j += 8) {
        int n = n0 + ty + j, k = k0 + tx;
        float v = t[tx][ty + j];
        __nv_bfloat16 h = __float2bfloat16(v);
        __nv_bfloat16 l = __float2bfloat16(v - __bfloat162float(h));
        size_t b = (size_t)n * KP + k;
        gbh[b]        = h;
        gbh[b + 1024] = h;
        gbh[b + 2048] = l;
    }
}

// ---------------- mma.sync bf16 GEMM -----------------------------------------
// CTA 128x128, 8 warps (4M x 2N), warp tile 32x64, BK=32, 4-stage cp.async,
// lookahead-2 (80KB smem -> 2 CTAs/SM). COMMITTED CONFIG — see NOTE 3.
#define ROWB 40
#define NCH  (KP / 32)        // 96 chunks
#define STG_BYTES (128 * 80)  // 10240 per tensor per stage
#define SMEM_DYN (4 * 2 * STG_BYTES)   // 81920

__device__ __forceinline__ int a_koff(int cn) {
    return (((cn >> 5) == 1) ? 2048 : 0) + (cn & 31) * 64;
}

template<int MODE>
__global__ void __launch_bounds__(256, 2) gemm_mma(const float* __restrict__ bias0,
                                                   const float* __restrict__ bias1,
                                                   float* __restrict__ outp) {
    extern __shared__ char dsm[];
    uint32_t smemA = s2u(dsm);                    // 4 stages x 10240
    uint32_t smemB = smemA + 4 * STG_BYTES;       // 4 stages x 10240

    const __nv_bfloat16* __restrict__ Ap =
        (const __nv_bfloat16*)((MODE == 0) ? g_sx : g_sh);
    const __nv_bfloat16* __restrict__ Bp = (MODE == 0) ? g_bh0 : g_bh1;
    int tid  = threadIdx.x;
    int lane = tid & 31, w = tid >> 5;
    int wm = w >> 1, wn = w & 1;
    int g = lane >> 2, tig = lane & 3;
    int row0 = blockIdx.y * 128, col0 = blockIdx.x * 128;

    int r0 = tid >> 2;
    int u0b = (tid & 3) * 16;
    int r1 = r0 + 64;
    int ra0 = row0 + r0; if (ra0 >= N_NODES) ra0 = N_NODES - 1;
    int ra1 = row0 + r1; if (ra1 >= N_NODES) ra1 = N_NODES - 1;
    const char* srcA0 = (const char*)(Ap + (size_t)ra0 * 2048) + u0b;
    const char* srcA1 = (const char*)(Ap + (size_t)ra1 * 2048) + u0b;
    const char* srcB0 = (const char*)(Bp + (size_t)(col0 + r0) * KP) + u0b;
    const char* srcB1 = (const char*)(Bp + (size_t)(col0 + r1) * KP) + u0b;
    uint32_t dst0 = (uint32_t)(r0 * 80 + u0b);
    uint32_t dst1 = (uint32_t)(r1 * 80 + u0b);

    int quad = lane >> 3, rin = lane & 7;
    uint32_t aLane = (uint32_t)((wm * 32 + (quad & 1) * 8 + rin) * 80 + (quad >> 1) * 16);
    uint32_t bLane = (uint32_t)((wn * 64 + (quad >> 1) * 8 + rin) * 80 + (quad & 1) * 16);

    float acc[2][8][4];
    #pragma unroll
    for (int m = 0; m < 2; m++)
        #pragma unroll
        for (int n = 0; n < 8; n++)
            #pragma unroll
            for (int q = 0; q < 4; q++) acc[m][n][q] = 0.f;

#define LOADCHUNK(cn, st) do {                                            \
        uint32_t as_ = smemA + (st) * STG_BYTES;                          \
        uint32_t bs_ = smemB + (st) * STG_BYTES;                          \
        int ka_ = a_koff(cn);                                             \
        CPA16(as_ + dst0, srcA0 + ka_);                                   \
        CPA16(as_ + dst1, srcA1 + ka_);                                   \
        CPA16(bs_ + dst0, srcB0 + (size_t)(cn) * 64);                     \
        CPA16(bs_ + dst1, srcB1 + (size_t)(cn) * 64);                     \
        asm volatile("cp.async.commit_group;" ::: "memory");              \
    } while (0)

    // prologue: stages 0,1
    LOADCHUNK(0, 0);
    LOADCHUNK(1, 1);

    #pragma unroll 1
    for (int c = 0; c < NCH; c++) {
        int s = c & 3;
        if (c + 2 < NCH) LOADCHUNK(c + 2, (c + 2) & 3);
        if      (c + 2 < NCH) asm volatile("cp.async.wait_group 2;" ::: "memory");
        else if (c + 1 < NCH) asm volatile("cp.async.wait_group 1;" ::: "memory");
        else                  asm volatile("cp.async.wait_group 0;" ::: "memory");
        __syncthreads();

        uint32_t aBase = smemA + s * STG_BYTES + aLane;
        uint32_t bBase = smemB + s * STG_BYTES + bLane;
        #pragma unroll
        for (int kt = 0; kt < 2; kt++) {
            uint32_t af[2][4];
            ldsm4(af[0], aBase + kt * 32);
            ldsm4(af[1], aBase + 16 * 80 + kt * 32);
            #pragma unroll
            for (int np = 0; np < 4; np++) {
                uint32_t bq[4];
                ldsm4(bq, bBase + np * (16 * 80) + kt * 32);
                #pragma unroll
                for (int mt = 0; mt < 2; mt++) {
                    mma16816(acc[mt][np * 2],     af[mt], bq);
                    mma16816(acc[mt][np * 2 + 1], af[mt], bq + 2);
                }
            }
        }
    }
#undef LOADCHUNK

    // ---- epilogue ----
    #pragma unroll
    for (int mt = 0; mt < 2; mt++) {
        int rlo = row0 + wm * 32 + mt * 16 + g;
        #pragma unroll
        for (int half = 0; half < 2; half++) {
            int row = rlo + half * 8;
            if (row >= N_NODES) continue;
            #pragma unroll
            for (int nt = 0; nt < 8; nt++) {
                int cca = col0 + wn * 64 + nt * 8 + tig * 2;
                float b0, b1v;
                if (MODE == 0) { b0 = __ldg(&bias0[cca]); b1v = __ldg(&bias0[cca + 1]); }
                else if (cca < 512) { b0 = __ldg(&bias0[cca]); b1v = __ldg(&bias0[cca + 1]); }
                else { b0 = __ldg(&bias1[cca - 512]); b1v = __ldg(&bias1[cca - 511]); }
                float v0 = acc[mt][nt][half * 2]     + b0;
                float v1 = acc[mt][nt][half * 2 + 1] + b1v;
                if (MODE == 0) {
                    v0 = (v0 > 0.f) ? v0 : 0.1f * v0;
                    v1 = (v1 > 0.f) ? v1 : 0.1f * v1;
                    *(float2*)&g_h[(size_t)row * 1024 + cca] = make_float2(v0, v1);
                } else {
                    if (cca < C_OUT) {
                        *(float2*)&outp[(size_t)row * C_OUT + cca]        = make_float2(v0, v1);
                        *(float2*)&outp[NOUT + (size_t)row * C_OUT + cca] = make_float2(v0, v1);
                    } else {
                        *(float2*)&outp[2 * NOUT + (size_t)row * C_OUT + (cca - C_OUT)]
                            = make_float2(v0, v1);
                    }
                }
            }
        }
    }
}

// ---------------- launcher --------------------------------------------------
// Capture-fork pattern: side streams join via events recorded on the origin
// (capturing) stream. Streams/events are created on the first call — the
// correctness run, which is NOT captured — and reused; the launched work is
// identical on every call.
extern "C" void kernel_launch(void* const* d_in, const int* in_sizes, int n_in,
                              void* d_out, int out_size) {
    const float* x   = (const float*)d_in[0];
    const void*  ei  = d_in[1];
    const float* W1  = (const float*)d_in[2];
    const float* b1  = (const float*)d_in[3];
    const float* Wm  = (const float*)d_in[4];
    const float* bm  = (const float*)d_in[5];
    const float* Ws  = (const float*)d_in[6];
    const float* bs  = (const float*)d_in[7];
    const float* gw  = (const float*)d_in[8];
    const float* gb  = (const float*)d_in[9];
    const float* gms = (const float*)d_in[10];
    float* out = (float*)d_out;

    static cudaStream_t sB = nullptr, sC = nullptr;
    static cudaEvent_t eFork, eStats, eB0, eB1;
    if (sB == nullptr) {
        cudaStreamCreateWithFlags(&sB, cudaStreamNonBlocking);
        cudaStreamCreateWithFlags(&sC, cudaStreamNonBlocking);
        cudaEventCreateWithFlags(&eFork,  cudaEventDisableTiming);
        cudaEventCreateWithFlags(&eStats, cudaEventDisableTiming);
        cudaEventCreateWithFlags(&eB0,    cudaEventDisableTiming);
        cudaEventCreateWithFlags(&eB1,    cudaEventDisableTiming);
        cudaFuncSetAttribute(gemm_mma<0>, cudaFuncAttributeMaxDynamicSharedMemorySize, SMEM_DYN);
        cudaFuncSetAttribute(gemm_mma<1>, cudaFuncAttributeMaxDynamicSharedMemorySize, SMEM_DYN);
    }

    dim3 gg(1024 / 128, (N_NODES + 127) / 128);   // (8, 79)

    // main stream: zeroing (needed by both branches), then fork
    zero_k<<<40, 256>>>();
    cudaEventRecord(eFork, 0);
    cudaStreamWaitEvent(sB, eFork, 0);
    cudaStreamWaitEvent(sC, eFork, 0);

    // branch B: GraphNorm stats (independent of edges)
    colstats_k<<<dim3(4, 400), 256, 0, sB>>>(x);
    stats_k  <<<4, 256, 0, sB>>>(gw, gb, gms);
    cudaEventRecord(eStats, sB);

    // branch C: both weight conversions (independent of everything else)
    convB_k<0><<<dim3(32, 32), dim3(32, 8), 0, sC>>>(W1, nullptr);
    cudaEventRecord(eB0, sC);
    convB_k<1><<<dim3(32, 32), dim3(32, 8), 0, sC>>>(Wm, Ws);
    cudaEventRecord(eB1, sC);

    // main: edge prep chain
    detect_k <<<(N_EDGES + 255) / 256, 256>>>((const long long*)ei);
    convert_k<<<(2 * N_EDGES + 255) / 256, 256>>>(ei);   // + fused deg
    scan_k   <<<1, 1024>>>();                            // + fused dis
    scatter_k<<<(N_EDGES + 255) / 256, 256>>>();

    // join: spmm0 needs stats; gemm0 needs convB0; gemm1 needs convB1
    cudaStreamWaitEvent(0, eStats, 0);
    spmm_pull<0><<<N_NODES, 256>>>(x);                   // + fused GraphNorm -> bf16 A in g_sx
    cudaStreamWaitEvent(0, eB0, 0);
    gemm_mma<0><<<gg, 256, SMEM_DYN>>>(b1, nullptr, nullptr);
    spmm_pull<1><<<N_NODES, 256>>>(nullptr);             // -> bf16 A in g_sh
    cudaStreamWaitEvent(0, eB1, 0);
    gemm_mma<1><<<gg, 256, SMEM_DYN>>>(bm, bs, out);
}

// round 16
// speedup vs baseline: 1.1967x; 1.0402x over previous
#include <cuda_runtime.h>
#include <cuda_bf16.h>
#include <cstdint>

#define N_NODES 10000
#define N_EDGES 160000
#define C_IN    1024
#define C_OUT   512
#define KP      3072                       // 3-way split K'
#define NOUT    ((size_t)N_NODES * C_OUT)

// ---------------- scratch (static device globals; no allocations) ----------
// NOTE 1: module-static budget is load-bearing (~170 MB works, 230 MB breaks
// module load). Statics ~137 MB.
// NOTE 2: never pass g_* globals as kernel args from host code (host-side
// shadow address + ATS = silent garbage). Reference them in device code only.
// NOTE 3: GEMM config committed: 128x128 CTA, 256 thr, 4-stage/80KB
// (2 CTAs/SM). R11 (100KB->1 CTA/SM) and R14 (512-thr CTA) both regressed;
// GEMM is mma.sync-pipe-bound.
// NOTE 4: SpMM loop committed as-is: R15's data prefetch regressed 17us
// (register pressure); it is L2-throughput-bound with ample TLP.
__device__ float g_sx   [(size_t)N_NODES * C_IN];   // bf16 [hi|lo] A for GEMM0 (written by spmm)
__device__ float g_h    [(size_t)N_NODES * 1024];   // fp32 hidden
__device__ float g_sh   [(size_t)N_NODES * 1024];   // bf16 [hi|lo] A for GEMM1 (written by spmm)
__device__ float g_colsum [C_IN];
__device__ float g_colsum2[C_IN];
__device__ float g_A[C_IN];
__device__ float g_B[C_IN];
__device__ float g_dis[N_NODES];
__device__ int   g_deg[N_NODES];
__device__ int   g_ei32[2 * N_EDGES];
__device__ int   g_flag32;
// CSR by destination
__device__ int   g_rowptr[N_NODES + 1];
__device__ int   g_cursor[N_NODES];
__device__ int   g_esrc[N_EDGES];
__device__ float g_ew  [N_EDGES];
// bf16 B operands [n][k'], K-segments [hi, hi, lo]; two buffers so both
// convB's can run concurrently on a side stream (6.3 MB each)
__device__ __nv_bfloat16 g_bh0[(size_t)1024 * KP];
__device__ __nv_bfloat16 g_bh1[(size_t)1024 * KP];

// ---------------- asm helpers ------------------------------------------------
__device__ __forceinline__ uint32_t s2u(const void* p) {
    uint32_t a;
    asm("{ .reg .u64 t; cvta.to.shared.u64 t, %1; cvt.u32.u64 %0, t; }"
        : "=r"(a) : "l"(p));
    return a;
}
__device__ __forceinline__ void ldsm4(uint32_t* r, uint32_t addr) {
    asm volatile("ldmatrix.sync.aligned.m8n8.x4.shared.b16 {%0,%1,%2,%3}, [%4];"
                 : "=r"(r[0]), "=r"(r[1]), "=r"(r[2]), "=r"(r[3]) : "r"(addr));
}
__device__ __forceinline__ void mma16816(float* d, const uint32_t* a, const uint32_t* b) {
    asm volatile(
        "mma.sync.aligned.m16n8k16.row.col.f32.bf16.bf16.f32 "
        "{%0,%1,%2,%3}, {%4,%5,%6,%7}, {%8,%9}, {%0,%1,%2,%3};"
        : "+f"(d[0]), "+f"(d[1]), "+f"(d[2]), "+f"(d[3])
        : "r"(a[0]), "r"(a[1]), "r"(a[2]), "r"(a[3]), "r"(b[0]), "r"(b[1]));
}
#define CPA16(dst, src) \
    asm volatile("cp.async.cg.shared.global [%0], [%1], 16;" \
                 :: "r"(dst), "l"(src))

// ---------------- setup kernels --------------------------------------------
__global__ void zero_k() {
    int i = blockIdx.x * blockDim.x + threadIdx.x;
    if (i < C_IN)    { g_colsum[i] = 0.f; g_colsum2[i] = 0.f; }
    if (i < N_NODES) { g_deg[i] = 0; }
    if (i == 0)      { g_flag32 = 0; }
}

// dtype detect from a 256-element prefix. int32 data reinterpreted as int64
// only stays in [0,N) when the odd word is 0 (P ~ 1e-4 per element); all 256
// aliasing is P ~ 1e-980. Single block.
__global__ void detect_k(const long long* __restrict__ ei) {
    int i = threadIdx.x;
    long long v = ei[i];
    if (v < 0 || v >= N_NODES) atomicOr(&g_flag32, 1);
}

// convert + fused degree histogram (dst half)
__global__ void convert_k(const void* __restrict__ ei) {
    int i = blockIdx.x * blockDim.x + threadIdx.x;
    if (i >= 2 * N_EDGES) return;
    int v = g_flag32 ? ((const int*)ei)[i]
                     : (int)((const long long*)ei)[i];
    g_ei32[i] = v;
    if (i >= N_EDGES) atomicAdd(&g_deg[v], 1);
}

__global__ void colstats_k(const float* __restrict__ x) {
    int col = blockIdx.x * 256 + threadIdx.x;
    int r0  = blockIdx.y * 25;
    float s = 0.f, s2 = 0.f;
    for (int r = r0; r < r0 + 25; r++) {
        float v = x[(size_t)r * C_IN + col];
        s += v; s2 += v * v;
    }
    atomicAdd(&g_colsum[col], s);
    atomicAdd(&g_colsum2[col], s2);
}

__global__ void stats_k(const float* __restrict__ w, const float* __restrict__ b,
                        const float* __restrict__ ms) {
    int j = blockIdx.x * blockDim.x + threadIdx.x;
    if (j >= C_IN) return;
    float m   = g_colsum[j]  * (1.f / N_NODES);
    float ex2 = g_colsum2[j] * (1.f / N_NODES);
    float s   = ms[j];
    float var = ex2 - 2.f * s * m * m + s * s * m * m;
    float Aj  = rsqrtf(var + 1e-5f) * w[j];
    g_A[j] = Aj;
    g_B[j] = b[j] - s * m * Aj;
}

// Single-block exclusive scan of g_deg -> rowptr/cursor; fused g_dis compute.
// Warp-shuffle scan: 2 barriers instead of 20.
__global__ void scan_k() {
    __shared__ int wsum[32];
    int t = threadIdx.x;
    int lane = t & 31, wid = t >> 5;
    int base = t * 10;
    int loc[10];
    int sum = 0;
    #pragma unroll
    for (int i = 0; i < 10; i++) {
        int idx = base + i;
        int v = (idx < N_NODES) ? g_deg[idx] : 0;
        if (idx < N_NODES) g_dis[idx] = rsqrtf((float)v + 1.0f);
        loc[i] = sum;
        sum += v;
    }
    // warp inclusive scan of per-thread sums
    int incl = sum;
    #pragma unroll
    for (int off = 1; off < 32; off <<= 1) {
        int n = __shfl_up_sync(0xffffffffu, incl, off);
        if (lane >= off) incl += n;
    }
    if (lane == 31) wsum[wid] = incl;
    __syncthreads();
    if (wid == 0) {
        int v = wsum[lane];
        int wincl = v;
        #pragma unroll
        for (int off = 1; off < 32; off <<= 1) {
            int n = __shfl_up_sync(0xffffffffu, wincl, off);
            if (lane >= off) wincl += n;
        }
        wsum[lane] = wincl;
    }
    __syncthreads();
    int excl = incl - sum + ((wid > 0) ? wsum[wid - 1] : 0);
    #pragma unroll
    for (int i = 0; i < 10; i++) {
        int idx = base + i;
        if (idx < N_NODES) {
            int p = excl + loc[i];
            g_rowptr[idx] = p;
            g_cursor[idx] = p;
        }
    }
    if (t == 1023) g_rowptr[N_NODES] = wsum[31];
}

__global__ void scatter_k() {
    int e = blockIdx.x * blockDim.x + threadIdx.x;
    if (e >= N_EDGES) return;
    int s = g_ei32[e];
    int d = g_ei32[N_EDGES + e];
    int pos = atomicAdd(&g_cursor[d], 1);
    g_esrc[pos] = s;
    g_ew[pos]   = g_dis[s] * g_dis[d];
}

// CSR pull SpMM fused with bf16 [hi|lo] split.  COMMITTED LOOP — see NOTE 4.
// PH 0: feat = raw x, GraphNorm fused by linearity:
//       sum w*(A∘x+B) = A∘(sum w*x) + (sum w)*B
// PH 1: feat = g_h (fp32 hidden), no norm.
template<int PH>
__global__ __launch_bounds__(256) void spmm_pull(const float* __restrict__ xin) {
    const float4* __restrict__ feat = (PH == 0) ? (const float4*)xin
                                                : (const float4*)g_h;
    __nv_bfloat16* __restrict__ out = (__nv_bfloat16*)((PH == 0) ? g_sx : g_sh);
    int d = blockIdx.x;
    int t = threadIdx.x;
    int beg = g_rowptr[d], end = g_rowptr[d + 1];
    float dd = g_dis[d]; dd *= dd;
    float4 v0 = feat[(size_t)d * 256 + t];
    float4 acc = make_float4(dd * v0.x, dd * v0.y, dd * v0.z, dd * v0.w);
    float wsum = dd;
    int   sn = (beg < end) ? __ldg(&g_esrc[beg]) : 0;
    float wn = (beg < end) ? __ldg(&g_ew[beg])   : 0.f;
    for (int j = beg; j < end; j++) {
        int s = sn; float w = wn;
        if (j + 1 < end) { sn = __ldg(&g_esrc[j + 1]); wn = __ldg(&g_ew[j + 1]); }
        float4 v = feat[(size_t)s * 256 + t];
        acc.x = fmaf(w, v.x, acc.x);
        acc.y = fmaf(w, v.y, acc.y);
        acc.z = fmaf(w, v.z, acc.z);
        acc.w = fmaf(w, v.w, acc.w);
        wsum += w;
    }
    if (PH == 0) {
        float4 Av = ((const float4*)g_A)[t];
        float4 Bv = ((const float4*)g_B)[t];
        acc.x = fmaf(Av.x, acc.x, wsum * Bv.x);
        acc.y = fmaf(Av.y, acc.y, wsum * Bv.y);
        acc.z = fmaf(Av.z, acc.z, wsum * Bv.z);
        acc.w = fmaf(Av.w, acc.w, wsum * Bv.w);
    }
    __nv_bfloat162 h01 = __floats2bfloat162_rn(acc.x, acc.y);
    __nv_bfloat162 h23 = __floats2bfloat162_rn(acc.z, acc.w);
    __nv_bfloat162 l01 = __floats2bfloat162_rn(acc.x - __low2float(h01),
                                               acc.y - __high2float(h01));
    __nv_bfloat162 l23 = __floats2bfloat162_rn(acc.z - __low2float(h23),
                                               acc.w - __high2float(h23));
    __nv_bfloat16* base = out + (size_t)d * 2048;
    uint2 hv, lv;
    hv.x = *(uint32_t*)&h01; hv.y = *(uint32_t*)&h23;
    lv.x = *(uint32_t*)&l01; lv.y = *(uint32_t*)&l23;
    *(uint2*)(base + t * 4)        = hv;
    *(uint2*)(base + 1024 + t * 4) = lv;
}

// ---------------- B conversion: fp32 W [k][n] -> g_bhX [n][3072] [hi,hi,lo] --
template<int MODE>
__global__ void convB_k(const float* __restrict__ p0, const float* __restrict__ p1) {
    __nv_bfloat16* __restrict__ gbh = (MODE == 0) ? g_bh0 : g_bh1;
    __shared__ float t[32][33];
    int n0 = blockIdx.x * 32, k0 = blockIdx.y * 32;
    int tx = threadIdx.x, ty = threadIdx.y;         // block (32, 8)
    #pragma unroll
    for (int j = 0; j < 32; j += 8) {
        int k = k0 + ty + j, n = n0 + tx;
        float v;
        if (MODE == 0) v = p0[(size_t)k * 1024 + n];
        else           v = (n < 512) ? p0[(size_t)k * 512 + n]
                                     : p1[(size_t)k * 512 + (n - 512)];
        t[ty + j][tx] = v;
    }
    __syncthreads();
    #pragma unroll
    for (int j = 0; j < 32; j += 8) {
        int n = n0 + ty + j, k = k0 + tx;
        float v = t[tx][ty + j];
        __nv_bfloat16 h = __float2bfloat16(v);
        __nv_bfloat16 l = __float2bfloat16(v - __bfloat162float(h));
        size_t b = (size_t)n * KP + k;
        gbh[b]        = h;
        gbh[b + 1024] = h;
        gbh[b + 2048] = l;
    }
}

// ---------------- mma.sync bf16 GEMM -----------------------------------------
// CTA 128x128, 8 warps (4M x 2N), warp tile 32x64, BK=32, 4-stage cp.async,
// lookahead-2 (80KB smem -> 2 CTAs/SM). COMMITTED CONFIG — see NOTE 3.
#define ROWB 40
#define NCH  (KP / 32)        // 96 chunks
#define STG_BYTES (128 * 80)  // 10240 per tensor per stage
#define SMEM_DYN (4 * 2 * STG_BYTES)   // 81920

__device__ __forceinline__ int a_koff(int cn) {
    return (((cn >> 5) == 1) ? 2048 : 0) + (cn & 31) * 64;
}

template<int MODE>
__global__ void __launch_bounds__(256, 2) gemm_mma(const float* __restrict__ bias0,
                                                   const float* __restrict__ bias1,
                                                   float* __restrict__ outp) {
    extern __shared__ char dsm[];
    uint32_t smemA = s2u(dsm);                    // 4 stages x 10240
    uint32_t smemB = smemA + 4 * STG_BYTES;       // 4 stages x 10240

    const __nv_bfloat16* __restrict__ Ap =
        (const __nv_bfloat16*)((MODE == 0) ? g_sx : g_sh);
    const __nv_bfloat16* __restrict__ Bp = (MODE == 0) ? g_bh0 : g_bh1;
    int tid  = threadIdx.x;
    int lane = tid & 31, w = tid >> 5;
    int wm = w >> 1, wn = w & 1;
    int g = lane >> 2, tig = lane & 3;
    int row0 = blockIdx.y * 128, col0 = blockIdx.x * 128;

    int r0 = tid >> 2;
    int u0b = (tid & 3) * 16;
    int r1 = r0 + 64;
    int ra0 = row0 + r0; if (ra0 >= N_NODES) ra0 = N_NODES - 1;
    int ra1 = row0 + r1; if (ra1 >= N_NODES) ra1 = N_NODES - 1;
    const char* srcA0 = (const char*)(Ap + (size_t)ra0 * 2048) + u0b;
    const char* srcA1 = (const char*)(Ap + (size_t)ra1 * 2048) + u0b;
    const char* srcB0 = (const char*)(Bp + (size_t)(col0 + r0) * KP) + u0b;
    const char* srcB1 = (const char*)(Bp + (size_t)(col0 + r1) * KP) + u0b;
    uint32_t dst0 = (uint32_t)(r0 * 80 + u0b);
    uint32_t dst1 = (uint32_t)(r1 * 80 + u0b);

    int quad = lane >> 3, rin = lane & 7;
    uint32_t aLane = (uint32_t)((wm * 32 + (quad & 1) * 8 + rin) * 80 + (quad >> 1) * 16);
    uint32_t bLane = (uint32_t)((wn * 64 + (quad >> 1) * 8 + rin) * 80 + (quad & 1) * 16);

    float acc[2][8][4];
    #pragma unroll
    for (int m = 0; m < 2; m++)
        #pragma unroll
        for (int n = 0; n < 8; n++)
            #pragma unroll
            for (int q = 0; q < 4; q++) acc[m][n][q] = 0.f;

#define LOADCHUNK(cn, st) do {                                            \
        uint32_t as_ = smemA + (st) * STG_BYTES;                          \
        uint32_t bs_ = smemB + (st) * STG_BYTES;                          \
        int ka_ = a_koff(cn);                                             \
        CPA16(as_ + dst0, srcA0 + ka_);                                   \
        CPA16(as_ + dst1, srcA1 + ka_);                                   \
        CPA16(bs_ + dst0, srcB0 + (size_t)(cn) * 64);                     \
        CPA16(bs_ + dst1, srcB1 + (size_t)(cn) * 64);                     \
        asm volatile("cp.async.commit_group;" ::: "memory");              \
    } while (0)

    // prologue: stages 0,1
    LOADCHUNK(0, 0);
    LOADCHUNK(1, 1);

    #pragma unroll 1
    for (int c = 0; c < NCH; c++) {
        int s = c & 3;
        if (c + 2 < NCH) LOADCHUNK(c + 2, (c + 2) & 3);
        if      (c + 2 < NCH) asm volatile("cp.async.wait_group 2;" ::: "memory");
        else if (c + 1 < NCH) asm volatile("cp.async.wait_group 1;" ::: "memory");
        else                  asm volatile("cp.async.wait_group 0;" ::: "memory");
        __syncthreads();

        uint32_t aBase = smemA + s * STG_BYTES + aLane;
        uint32_t bBase = smemB + s * STG_BYTES + bLane;
        #pragma unroll
        for (int kt = 0; kt < 2; kt++) {
            uint32_t af[2][4];
            ldsm4(af[0], aBase + kt * 32);
            ldsm4(af[1], aBase + 16 * 80 + kt * 32);
            #pragma unroll
            for (int np = 0; np < 4; np++) {
                uint32_t bq[4];
                ldsm4(bq, bBase + np * (16 * 80) + kt * 32);
                #pragma unroll
                for (int mt = 0; mt < 2; mt++) {
                    mma16816(acc[mt][np * 2],     af[mt], bq);
                    mma16816(acc[mt][np * 2 + 1], af[mt], bq + 2);
                }
            }
        }
    }
#undef LOADCHUNK

    // ---- epilogue ----
    #pragma unroll
    for (int mt = 0; mt < 2; mt++) {
        int rlo = row0 + wm * 32 + mt * 16 + g;
        #pragma unroll
        for (int half = 0; half < 2; half++) {
            int row = rlo + half * 8;
            if (row >= N_NODES) continue;
            #pragma unroll
            for (int nt = 0; nt < 8; nt++) {
                int cca = col0 + wn * 64 + nt * 8 + tig * 2;
                float b0, b1v;
                if (MODE == 0) { b0 = __ldg(&bias0[cca]); b1v = __ldg(&bias0[cca + 1]); }
                else if (cca < 512) { b0 = __ldg(&bias0[cca]); b1v = __ldg(&bias0[cca + 1]); }
                else { b0 = __ldg(&bias1[cca - 512]); b1v = __ldg(&bias1[cca - 511]); }
                float v0 = acc[mt][nt][half * 2]     + b0;
                float v1 = acc[mt][nt][half * 2 + 1] + b1v;
                if (MODE == 0) {
                    v0 = (v0 > 0.f) ? v0 : 0.1f * v0;
                    v1 = (v1 > 0.f) ? v1 : 0.1f * v1;
                    *(float2*)&g_h[(size_t)row * 1024 + cca] = make_float2(v0, v1);
                } else {
                    if (cca < C_OUT) {
                        *(float2*)&outp[(size_t)row * C_OUT + cca]        = make_float2(v0, v1);
                        *(float2*)&outp[NOUT + (size_t)row * C_OUT + cca] = make_float2(v0, v1);
                    } else {
                        *(float2*)&outp[2 * NOUT + (size_t)row * C_OUT + (cca - C_OUT)]
                            = make_float2(v0, v1);
                    }
                }
            }
        }
    }
}

// ---------------- launcher --------------------------------------------------
// Capture-fork pattern: side streams join via events recorded on the origin
// (capturing) stream. Streams/events are created on the first call — the
// correctness run, which is NOT captured — and reused; the launched work is
// identical on every call.
extern "C" void kernel_launch(void* const* d_in, const int* in_sizes, int n_in,
                              void* d_out, int out_size) {
    const float* x   = (const float*)d_in[0];
    const void*  ei  = d_in[1];
    const float* W1  = (const float*)d_in[2];
    const float* b1  = (const float*)d_in[3];
    const float* Wm  = (const float*)d_in[4];
    const float* bm  = (const float*)d_in[5];
    const float* Ws  = (const float*)d_in[6];
    const float* bs  = (const float*)d_in[7];
    const float* gw  = (const float*)d_in[8];
    const float* gb  = (const float*)d_in[9];
    const float* gms = (const float*)d_in[10];
    float* out = (float*)d_out;

    static cudaStream_t sB = nullptr, sC = nullptr;
    static cudaEvent_t eFork, eStats, eB0, eB1;
    if (sB == nullptr) {
        cudaStreamCreateWithFlags(&sB, cudaStreamNonBlocking);
        cudaStreamCreateWithFlags(&sC, cudaStreamNonBlocking);
        cudaEventCreateWithFlags(&eFork,  cudaEventDisableTiming);
        cudaEventCreateWithFlags(&eStats, cudaEventDisableTiming);
        cudaEventCreateWithFlags(&eB0,    cudaEventDisableTiming);
        cudaEventCreateWithFlags(&eB1,    cudaEventDisableTiming);
        cudaFuncSetAttribute(gemm_mma<0>, cudaFuncAttributeMaxDynamicSharedMemorySize, SMEM_DYN);
        cudaFuncSetAttribute(gemm_mma<1>, cudaFuncAttributeMaxDynamicSharedMemorySize, SMEM_DYN);
    }

    dim3 gg(1024 / 128, (N_NODES + 127) / 128);   // (8, 79)

    // main stream: zeroing (needed by both branches), then fork
    zero_k<<<40, 256>>>();
    cudaEventRecord(eFork, 0);
    cudaStreamWaitEvent(sB, eFork, 0);
    cudaStreamWaitEvent(sC, eFork, 0);

    // branch B: GraphNorm stats (independent of edges)
    colstats_k<<<dim3(4, 400), 256, 0, sB>>>(x);
    stats_k  <<<4, 256, 0, sB>>>(gw, gb, gms);
    cudaEventRecord(eStats, sB);

    // branch C: both weight conversions (independent of everything else)
    convB_k<0><<<dim3(32, 32), dim3(32, 8), 0, sC>>>(W1, nullptr);
    cudaEventRecord(eB0, sC);
    convB_k<1><<<dim3(32, 32), dim3(32, 8), 0, sC>>>(Wm, Ws);
    cudaEventRecord(eB1, sC);

    // main: edge prep chain
    detect_k <<<1, 256>>>((const long long*)ei);
    convert_k<<<(2 * N_EDGES + 255) / 256, 256>>>(ei);   // + fused deg
    scan_k   <<<1, 1024>>>();                            // + fused dis
    scatter_k<<<(N_EDGES + 255) / 256, 256>>>();

    // join: spmm0 needs stats; gemm0 needs convB0; gemm1 needs convB1
    cudaStreamWaitEvent(0, eStats, 0);
    spmm_pull<0><<<N_NODES, 256>>>(x);                   // + fused GraphNorm -> bf16 A in g_sx
    cudaStreamWaitEvent(0, eB0, 0);
    gemm_mma<0><<<gg, 256, SMEM_DYN>>>(b1, nullptr, nullptr);
    spmm_pull<1><<<N_NODES, 256>>>(nullptr);             // -> bf16 A in g_sh
    cudaStreamWaitEvent(0, eB1, 0);
    gemm_mma<1><<<gg, 256, SMEM_DYN>>>(bm, bs, out);
}